// round 16
// baseline (speedup 1.0000x reference)
#include <cuda_runtime.h>
#include <stdint.h>

#define BATCH    512
#define NTOK     4096
#define HALF     2048
#define ROW_OUT  4097           // N + 1
#define THREADS  512
#define WARPS    16
#define EPT      4              // elements per thread (half row / 512)
#define SBUF     2112           // staging words: 2048 + alignment slack

__global__ __launch_bounds__(THREADS)
void triple_grain_half_kernel(const int* __restrict__ in0,
                              const int* __restrict__ in1,
                              float* __restrict__ out)
{
    const int cta  = blockIdx.x;
    const int b    = cta >> 1;          // row
    const int h    = cta & 1;           // half
    const int t    = threadIdx.x;
    const int lane = t & 31;
    const int wid  = t >> 5;

    __shared__ __align__(16) uint32_t spack[SBUF];
    __shared__ unsigned long long     warp_agg[WARPS];
    __shared__ unsigned long long     s_ored[WARPS];
    __shared__ int                    s_swapped;

    const size_t arr_stride = (size_t)BATCH * ROW_OUT;
    const size_t rowbase    = (size_t)b * ROW_OUT;

    // ---- 0. segment constant stores first (depend on nothing) ----
    {
        const int S = h ? HALF : 0;
        const int E = h ? ROW_OUT : HALF;
        #pragma unroll
        for (int k = 0; k < 3; k++) {
            float* __restrict__ sp = out + (size_t)(6 + k) * arr_stride + rowbase;
            const float kk = (float)k;
            const int a        = (4 - ((b + S) & 3)) & 3;     // global idx ≡ (b+s) mod 4
            const int head_end = min(S + a, E);
            for (int s = S + t; s < head_end; s += THREADS) sp[s] = kk;
            const int vstart = head_end;
            int nv = (E - vstart) >> 2; if (nv < 0) nv = 0;
            const float4 k4 = make_float4(kk, kk, kk, kk);
            for (int vi = t; vi < nv; vi += THREADS)
                *reinterpret_cast<float4*>(sp + vstart + vi * 4) = k4;
            for (int s = vstart + nv * 4 + t; s < E; s += THREADS) sp[s] = kk;
        }
    }

    // ---- 1. input-order detection ----
    if (t == 0) {
        int mx = 0;
        #pragma unroll
        for (int i = 0; i < 16; i++) mx = max(mx, in0[i * 17]);
        s_swapped = (mx <= 2) ? 1 : 0;
    }
    __syncthreads();
    const int* __restrict__ indices = s_swapped ? in1 : in0;
    const int* __restrict__ grains  = s_swapped ? in0 : in1;

    // ---- 2. loads: own half (indices+grains) + other half grains ----
    const int4 iv = reinterpret_cast<const int4*>(indices + (size_t)b * NTOK + h * HALF)[t];
    const int4 gv = reinterpret_cast<const int4*>(grains  + (size_t)b * NTOK + h * HALF)[t];
    const int4 ov = reinterpret_cast<const int4*>(grains  + (size_t)b * NTOK + (h ^ 1) * HALF)[t];

    int v[EPT] = { iv.x, iv.y, iv.z, iv.w };
    int g[EPT] = { gv.x, gv.y, gv.z, gv.w };
    int o[EPT] = { ov.x, ov.y, ov.z, ov.w };
    #pragma unroll
    for (int i = 0; i < EPT; i++) {
        g[i] = (g[i] == 1) ? 1 : ((g[i] == 2) ? 2 : 0);
        o[i] = (o[i] == 1) ? 1 : ((o[i] == 2) ? 2 : 0);
    }

    unsigned long long cnt = 0ULL, ocnt = 0ULL;
    #pragma unroll
    for (int i = 0; i < EPT; i++) {
        cnt  += 1ULL << (21 * g[i]);
        ocnt += 1ULL << (21 * o[i]);
    }

    // own-half inclusive scan (warp shuffle)
    unsigned long long incl = cnt;
    #pragma unroll
    for (int d = 1; d < 32; d <<= 1) {
        unsigned long long y = __shfl_up_sync(0xFFFFFFFFu, incl, d);
        if (lane >= d) incl += y;
    }
    // other-half warp reduction
    unsigned long long ored = ocnt;
    #pragma unroll
    for (int d = 16; d; d >>= 1) ored += __shfl_down_sync(0xFFFFFFFFu, ored, d);
    if (lane == 31) warp_agg[wid] = incl;
    if (lane == 0)  s_ored[wid]   = ored;
    __syncthreads();

    if (wid == 0) {
        unsigned long long w = (lane < WARPS) ? warp_agg[lane] : 0ULL;
        #pragma unroll
        for (int d = 1; d < WARPS; d <<= 1) {
            unsigned long long y = __shfl_up_sync(0xFFFFFFFFu, w, d);
            if (lane >= d) w += y;
        }
        if (lane < WARPS) warp_agg[lane] = w;
    } else if (wid == 1 && lane == 0) {
        unsigned long long s = 0ULL;
        #pragma unroll
        for (int i = 0; i < WARPS; i++) s += s_ored[i];
        s_ored[0] = s;
    }
    __syncthreads();

    const unsigned long long wexcl = wid ? warp_agg[wid - 1] : 0ULL;
    const unsigned long long excl  = wexcl + (incl - cnt);
    const unsigned long long mytot = warp_agg[WARPS - 1];
    const unsigned long long oth   = s_ored[0];

    int off0 = (int)( excl        & 0x1FFFFF);
    int off1 = (int)((excl >> 21) & 0x1FFFFF);
    int off2 = (int)((excl >> 42) & 0x1FFFFF);
    const int L0 = (int)( mytot        & 0x1FFFFF);
    const int L1 = (int)((mytot >> 21) & 0x1FFFFF);
    const int L2 = (int)((mytot >> 42) & 0x1FFFFF);
    const int oc0 = (int)( oth        & 0x1FFFFF);
    const int oc1 = (int)((oth >> 21) & 0x1FFFFF);
    const int oc2 = (int)((oth >> 42) & 0x1FFFFF);

    // global chunk starts and row totals (no inter-CTA comm needed)
    const int S0 = h ? oc0 : 0,  S1 = h ? oc1 : 0,  S2 = h ? oc2 : 0;
    const int T0 = L0 + oc0,     T1 = L1 + oc1,     T2 = L2 + oc2;

    // staging bases: lb_k ≡ (b + S_k) mod 4 so vector reads/writes align together
    const int lb0 = (b + S0) & 3;
    const int lb1 = ((lb0 + L0 + 3) & ~3) + ((b + S1) & 3);
    const int lb2 = ((lb1 + L1 + 3) & ~3) + ((b + S2) & 3);

    // ---- 3. scatter packed (content | pos<<16) into SMEM ----
    const int basepos = h * HALF + t * EPT;
    #pragma unroll
    for (int i = 0; i < EPT; i++) {
        const int gi = g[i];
        const int oo = (gi == 0) ? off0 : ((gi == 1) ? off1 : off2);
        if      (gi == 0) off0++;
        else if (gi == 1) off1++;
        else              off2++;
        const int lb = (gi == 0) ? lb0 : ((gi == 1) ? lb1 : lb2);
        spack[lb + oo] = (uint32_t)v[i] | ((uint32_t)(basepos + i) << 16);
    }
    __syncthreads();

    // per-class params (constant-indexed in unrolled loops -> registers)
    const int   Sarr[3]  = { S0, S1, S2 };
    const int   Larr[3]  = { L0, L1, L2 };
    const int   Tarr[3]  = { T0, T1, T2 };
    const int   lbarr[3] = { lb0, lb1, lb2 };
    const float ppads[3] = { 128.0f, 256.0f, 1024.0f };

    // ---- 4. data chunk write per class: [S, S+L) all compacted ----
    #pragma unroll
    for (int k = 0; k < 3; k++) {
        const int Sk = Sarr[k], Lk = Larr[k], lb = lbarr[k];
        const int E  = Sk + Lk;
        float* __restrict__ cp = out + (size_t)k * arr_stride + rowbase;
        float* __restrict__ pp = cp + 3 * arr_stride;
        const int a        = (4 - ((b + Sk) & 3)) & 3;
        const int head_end = min(Sk + a, E);
        for (int s = Sk + t; s < head_end; s += THREADS) {
            const uint32_t q = spack[lb + (s - Sk)];
            cp[s] = (float)(q & 0xFFFFu); pp[s] = (float)(q >> 16);
        }
        const int vstart = head_end;
        int nv = (E - vstart) >> 2; if (nv < 0) nv = 0;
        for (int vi = t; vi < nv; vi += THREADS) {
            const int s0 = vstart + vi * 4;
            const uint4 q = *reinterpret_cast<const uint4*>(spack + lb + (s0 - Sk));
            *reinterpret_cast<float4*>(cp + s0) =
                make_float4((float)(q.x & 0xFFFFu), (float)(q.y & 0xFFFFu),
                            (float)(q.z & 0xFFFFu), (float)(q.w & 0xFFFFu));
            *reinterpret_cast<float4*>(pp + s0) =
                make_float4((float)(q.x >> 16), (float)(q.y >> 16),
                            (float)(q.z >> 16), (float)(q.w >> 16));
        }
        for (int s = vstart + nv * 4 + t; s < E; s += THREADS) {
            const uint32_t q = spack[lb + (s - Sk)];
            cp[s] = (float)(q & 0xFFFFu); pp[s] = (float)(q >> 16);
        }
    }

    // ---- 5. EOS/PAD tail: [tot, ROW_OUT) split between the two half-CTAs ----
    #pragma unroll
    for (int k = 0; k < 3; k++) {
        const int   tk   = Tarr[k];
        const float ppad = ppads[k];
        const float peos = ppad + 1.0f;
        const int   mid  = tk + ((ROW_OUT - tk) >> 1);
        const int   Sc   = h ? mid : tk;
        const int   Ec   = h ? ROW_OUT : mid;
        float* __restrict__ cp = out + (size_t)k * arr_stride + rowbase;
        float* __restrict__ pp = cp + 3 * arr_stride;
        const int a        = (4 - ((b + Sc) & 3)) & 3;
        const int head_end = min(Sc + a, Ec);
        for (int s = Sc + t; s < head_end; s += THREADS) {
            const bool e = (s == tk);
            cp[s] = e ? 1025.0f : 1024.0f;
            pp[s] = e ? peos    : ppad;
        }
        const int vstart = head_end;
        int nv = (Ec - vstart) >> 2; if (nv < 0) nv = 0;
        const float4 cpad4 = make_float4(1024.0f, 1024.0f, 1024.0f, 1024.0f);
        const float4 ppad4 = make_float4(ppad, ppad, ppad, ppad);
        for (int vi = t; vi < nv; vi += THREADS) {
            const int s0 = vstart + vi * 4;
            float4 c4 = cpad4, p4 = ppad4;
            if (tk >= s0 && tk < s0 + 4) {     // group containing EOS (<=1 per class)
                float c[4], p[4];
                #pragma unroll
                for (int j = 0; j < 4; j++) {
                    const bool e = (s0 + j == tk);
                    c[j] = e ? 1025.0f : 1024.0f;
                    p[j] = e ? peos    : ppad;
                }
                c4 = make_float4(c[0], c[1], c[2], c[3]);
                p4 = make_float4(p[0], p[1], p[2], p[3]);
            }
            *reinterpret_cast<float4*>(cp + s0) = c4;
            *reinterpret_cast<float4*>(pp + s0) = p4;
        }
        for (int s = vstart + nv * 4 + t; s < Ec; s += THREADS) {
            const bool e = (s == tk);
            cp[s] = e ? 1025.0f : 1024.0f;
            pp[s] = e ? peos    : ppad;
        }
    }
}

extern "C" void kernel_launch(void* const* d_in, const int* in_sizes, int n_in,
                              void* d_out, int out_size) {
    const int* in0 = (const int*)d_in[0];   // [512, 64, 64] int32 (indices OR grains)
    const int* in1 = (const int*)d_in[1];   // [512, 64, 64] int32 (the other one)
    float* out = (float*)d_out;             // 9 x [512, 4097] float32, concatenated
    (void)in_sizes; (void)n_in; (void)out_size;
    triple_grain_half_kernel<<<BATCH * 2, THREADS>>>(in0, in1, out);
}

// round 17
// speedup vs baseline: 1.1810x; 1.1810x over previous
#include <cuda_runtime.h>
#include <stdint.h>

#define BATCH     512
#define NTOK      4096
#define ROW_OUT   4097          // N + 1
#define THREADS   512
#define WARPS     (THREADS / 32)
#define EPT       8             // elements per thread

__global__ __launch_bounds__(THREADS, 4)   // force <=32 regs -> 4 CTAs/SM -> whole grid in one wave
void triple_grain_permute_kernel(const int* __restrict__ in0,
                                 const int* __restrict__ in1,
                                 float* __restrict__ out)
{
    const int b    = blockIdx.x;
    const int t    = threadIdx.x;
    const int lane = t & 31;
    const int wid  = t >> 5;

    __shared__ __align__(16) uint32_t spack[NTOK + 16];  // packed (content | pos<<16), class-partitioned
    __shared__ unsigned long long     warp_agg[WARPS];
    __shared__ int                    s_swapped;

    // ---- input-order detection: which int32 buffer holds grain ids {0,1,2}? ----
    if (t == 0) {
        int mx = 0;
        #pragma unroll
        for (int i = 0; i < 16; i++) mx = max(mx, in0[i * 17]);
        s_swapped = (mx <= 2) ? 1 : 0;
    }
    __syncthreads();
    const int* __restrict__ indices = s_swapped ? in1 : in0;
    const int* __restrict__ grains  = s_swapped ? in0 : in1;

    // ---- load 8 values + 8 grain ids (vectorized int4) ----
    const int4* idx4 = reinterpret_cast<const int4*>(indices + (size_t)b * NTOK);
    const int4* grn4 = reinterpret_cast<const int4*>(grains  + (size_t)b * NTOK);
    int4 iv0 = idx4[t * 2 + 0];
    int4 iv1 = idx4[t * 2 + 1];
    int4 gv0 = grn4[t * 2 + 0];
    int4 gv1 = grn4[t * 2 + 1];

    int v[EPT] = { iv0.x, iv0.y, iv0.z, iv0.w, iv1.x, iv1.y, iv1.z, iv1.w };
    int g[EPT] = { gv0.x, gv0.y, gv0.z, gv0.w, gv1.x, gv1.y, gv1.z, gv1.w };

    #pragma unroll
    for (int i = 0; i < EPT; i++) {
        int gi = g[i];
        g[i] = (gi == 1) ? 1 : ((gi == 2) ? 2 : 0);
    }

    // ---- per-thread class counts packed 21 bits/class in one u64 ----
    unsigned long long cnt = 0ULL;
    #pragma unroll
    for (int i = 0; i < EPT; i++)
        cnt += 1ULL << (21 * g[i]);

    // ---- warp-shuffle inclusive scan ----
    unsigned long long incl = cnt;
    #pragma unroll
    for (int d = 1; d < 32; d <<= 1) {
        unsigned long long y = __shfl_up_sync(0xFFFFFFFFu, incl, d);
        if (lane >= d) incl += y;
    }
    if (lane == 31) warp_agg[wid] = incl;
    __syncthreads();

    if (wid == 0) {
        unsigned long long w = (lane < WARPS) ? warp_agg[lane] : 0ULL;
        #pragma unroll
        for (int d = 1; d < WARPS; d <<= 1) {
            unsigned long long y = __shfl_up_sync(0xFFFFFFFFu, w, d);
            if (lane >= d) w += y;
        }
        if (lane < WARPS) warp_agg[lane] = w;
    }
    __syncthreads();

    const unsigned long long warp_excl = (wid == 0) ? 0ULL : warp_agg[wid - 1];
    const unsigned long long excl      = warp_excl + (incl - cnt);
    const unsigned long long total     = warp_agg[WARPS - 1];

    int off0 = (int)( excl        & 0x1FFFFF);
    int off1 = (int)((excl >> 21) & 0x1FFFFF);
    int off2 = (int)((excl >> 42) & 0x1FFFFF);
    const int tot0 = (int)( total        & 0x1FFFFF);
    const int tot1 = (int)((total >> 21) & 0x1FFFFF);
    const int tot2 = (int)((total >> 42) & 0x1FFFFF);

    // global row alignment: first global-16B-aligned element index within the row
    const int align = (4 - (b & 3)) & 3;
    // class bases padded so (base + align) % 4 == 0  ->  aligned LDS.128 in the body
    const int pad0  = (4 - align) & 3;
    const int base0 = pad0;
    const int base1 = base0 + ((tot0 + 3) & ~3);
    const int base2 = base1 + ((tot1 + 3) & ~3);

    // ---- stage packed (content | pos<<16) into class-partitioned SMEM ----
    const int basepos = t * EPT;
    #pragma unroll
    for (int i = 0; i < EPT; i++) {
        const int gi = g[i];
        const int o  = (gi == 0) ? off0 : ((gi == 1) ? off1 : off2);
        if      (gi == 0) off0++;
        else if (gi == 1) off1++;
        else              off2++;
        const int base = (gi == 0) ? base0 : ((gi == 1) ? base1 : base2);
        spack[base + o] = (uint32_t)v[i] | ((uint32_t)(basepos + i) << 16);
    }
    __syncthreads();

    // ---- vectorized write-out of all 9 arrays ----
    const size_t arr_stride = (size_t)BATCH * ROW_OUT;     // divisible by 4
    const size_t rowbase    = (size_t)b * ROW_OUT;
    const int    nvec       = (ROW_OUT - align) >> 2;      // float4 groups
    const int    tail_start = align + nvec * 4;
    const int    tail_len   = ROW_OUT - tail_start;        // 0..3

    #pragma unroll
    for (int k = 0; k < 3; k++) {
        const int   tot  = (k == 0) ? tot0   : ((k == 1) ? tot1   : tot2);
        const int   base = (k == 0) ? base0  : ((k == 1) ? base1  : base2);
        const float ppad = (k == 0) ? 128.0f : ((k == 1) ? 256.0f : 1024.0f);
        const float peos = ppad + 1.0f;
        float* __restrict__ cp = out + (size_t)k * arr_stride + rowbase;  // content[k]
        float* __restrict__ pp = cp + 3 * arr_stride;                     // position[k]
        float* __restrict__ sp = out + (size_t)(6 + k) * arr_stride + rowbase;
        const float kk = (float)k;
        const float4 seg4  = make_float4(kk, kk, kk, kk);
        const float4 cpad4 = make_float4(1024.0f, 1024.0f, 1024.0f, 1024.0f);
        const float4 ppad4 = make_float4(ppad, ppad, ppad, ppad);

        // scalar head + tail (few threads, separate warps)
        if (t < align) {
            const int s = t;
            float cv, pv;
            if (s < tot)       { uint32_t p = spack[base + s]; cv = (float)(p & 0xFFFFu); pv = (float)(p >> 16); }
            else if (s == tot) { cv = 1025.0f; pv = peos; }
            else               { cv = 1024.0f; pv = ppad; }
            cp[s] = cv; pp[s] = pv; sp[s] = kk;
        } else if (t >= 32 && (t - 32) < tail_len) {
            const int s = tail_start + (t - 32);
            float cv, pv;
            if (s < tot)       { uint32_t p = spack[base + s]; cv = (float)(p & 0xFFFFu); pv = (float)(p >> 16); }
            else if (s == tot) { cv = 1025.0f; pv = peos; }
            else               { cv = 1024.0f; pv = ppad; }
            cp[s] = cv; pp[s] = pv; sp[s] = kk;
        }

        // vector body: per-group classification
        for (int vi = t; vi < nvec; vi += THREADS) {
            const int s0 = align + vi * 4;
            float4 c4, p4;
            if (s0 + 3 < tot) {
                // fully compacted: one aligned LDS.128, conflict-free
                const uint4 q = *reinterpret_cast<const uint4*>(spack + base + s0);
                c4 = make_float4((float)(q.x & 0xFFFFu), (float)(q.y & 0xFFFFu),
                                 (float)(q.z & 0xFFFFu), (float)(q.w & 0xFFFFu));
                p4 = make_float4((float)(q.x >> 16), (float)(q.y >> 16),
                                 (float)(q.z >> 16), (float)(q.w >> 16));
            } else if (s0 > tot) {
                // pure PAD: constants only, no SMEM read
                c4 = cpad4;
                p4 = ppad4;
            } else {
                // straddles tot (at most one group): per-element
                float c[4], p[4];
                #pragma unroll
                for (int j = 0; j < 4; j++) {
                    const int s = s0 + j;
                    if (s < tot)       { uint32_t q = spack[base + s]; c[j] = (float)(q & 0xFFFFu); p[j] = (float)(q >> 16); }
                    else if (s == tot) { c[j] = 1025.0f; p[j] = peos; }
                    else               { c[j] = 1024.0f; p[j] = ppad; }
                }
                c4 = make_float4(c[0], c[1], c[2], c[3]);
                p4 = make_float4(p[0], p[1], p[2], p[3]);
            }
            *reinterpret_cast<float4*>(cp + s0) = c4;
            *reinterpret_cast<float4*>(pp + s0) = p4;
            *reinterpret_cast<float4*>(sp + s0) = seg4;
        }
    }
}

extern "C" void kernel_launch(void* const* d_in, const int* in_sizes, int n_in,
                              void* d_out, int out_size) {
    const int* in0 = (const int*)d_in[0];   // [512, 64, 64] int32 (indices OR grains)
    const int* in1 = (const int*)d_in[1];   // [512, 64, 64] int32 (the other one)
    float* out = (float*)d_out;             // 9 x [512, 4097] float32, concatenated
    (void)in_sizes; (void)n_in; (void)out_size;
    triple_grain_permute_kernel<<<BATCH, THREADS>>>(in0, in1, out);
}